// round 13
// baseline (speedup 1.0000x reference)
#include <cuda_runtime.h>
#include <math.h>

// ---------------- problem constants ----------------
#define T_STEPS 16384
#define HD      1028
#define NT      512          // 16 warps: warp0 = control/tail, warps 1..15 compute
#define NCW     15           // compute warps

// Layer 0: 49 CTAs x 21 units (84 gate rows = 64 reg + 20 smem)
#define N0  49
#define U0  21
#define R0  84
#define RB0 20
// Layer 1: 94 CTAs x 11 units (44 gate rows = 32 reg + 12 smem)
#define N1  94
#define U1  11
#define R1  44
#define RB1 12

#define CPW 72               // cols per warp per (sub)vector: 15*72=1080 >= 1028
#define NIT 18               // CPW/4 float4 iters
#define CRQ 11               // reg-col float4 iters (44 cols in regs)
#define CRC 44
#define SCC 28               // smem cols per reg-row group (stride 28: conflict-free)

#define RING 4               // h ring depth (L0 may run up to 3 ahead)
#define RREP 4               // L2-slice replicas
#define RSTR 1088
#define NCTA (N0 + N1)       // 143 <= 148 SMs, all co-resident

// ---- L0 smem offsets (floats) ----
#define HS0   0
#define WA0   1080
#define WB0   (WA0 + NCW*2*32*SCC)     // 27960
#define PART0 (WB0 + NCW*RB0*76)       // 50760  ([2][15][96])
#define SUM0  (PART0 + 2*NCW*96)       // 53640
#define BIAS0 (SUM0 + 96)
#define WIH0  (BIAS0 + 96)
#define END0  (WIH0 + 96)              // 53928
// ---- L1 smem offsets ----
#define HSB   0
#define HSA   1080
#define WAB   2160
#define WAA   (WAB + NCW*32*SCC)       // 15600
#define WBM   (WAA + NCW*32*SCC)       // 29040  ([15][12][148]: B cols 0..71, A cols 72..143)
#define PART1 (WBM + NCW*RB1*148)      // 55680  ([2][15][48])
#define SUM1  (PART1 + 2*NCW*48)       // 57120
#define BIAS1 (SUM1 + 48)
#define END1  (BIAS1 + 48)             // 57216
#define SMEM_BYTES (END1 * 4)          // 228,864 B <= 227KB opt-in limit

// ---------------- device scratch ----------------
__device__ __align__(16) float g_ha[RING][RREP][RSTR];   // L0 outputs ring
__device__ __align__(16) float g_hb[RING][RREP][RSTR];   // L1 outputs ring
__device__ __align__(16) float g_h2[(long long)T_STEPS * HD];
__device__ unsigned g_cnts[64];   // [0]=cnt0 (L0 rounds), [32]=cnt1 (L1 rounds)

extern __shared__ float sm[];

#define FENCE_ACQ() asm volatile("fence.acq_rel.gpu;" ::: "memory")
#define RED_INC(p)  asm volatile("red.release.gpu.global.add.u32 [%0], %1;" :: "l"(p), "r"(1u) : "memory")

__device__ __forceinline__ void poll_ge(unsigned* p, unsigned tgt) {
    unsigned v;
    do {
        asm volatile("ld.relaxed.gpu.global.u32 %0, [%1];"
                     : "=r"(v) : "l"(p) : "memory");
    } while (v < tgt);
}

__device__ __forceinline__ float sigm(float v) { return 1.f / (1.f + expf(-v)); }

// ================= Layer 0 (49 CTAs) =================
// round t: wait cnt0>=t*N0 (ha[t-1] ready) and cnt1>=(t-3)*N1 (ring back-pressure),
// compute ha[t] from ha[t-1], publish to ring slot (t+1)&3, RED cnt0.
__device__ void run_l0(int cb,
                       const float* __restrict__ w_hh, const float* __restrict__ w_ih,
                       const float* __restrict__ bi,   const float* __restrict__ bh,
                       const float* __restrict__ x)
{
    const int tid = threadIdx.x, w = tid >> 5, l = tid & 31;
    const int cw = w - 1;
    const int c0 = cw * CPW;
    const int rep = cb & (RREP - 1);

    float wr[2][CRC];
    if (w >= 1) {
        #pragma unroll
        for (int g = 0; g < 2; ++g) {
            int r = g * 32 + l;                       // row 0..63
            int gate = r / U0, uu = r - gate * U0;
            int gu = cb * U0 + uu;
            const float* wrow = (gu < HD) ? &w_hh[(long long)(gate * HD + gu) * HD] : nullptr;
            #pragma unroll
            for (int j = 0; j < CRC; ++j) {
                int c = c0 + j;
                wr[g][j] = (wrow && c < HD) ? wrow[c] : 0.f;
            }
            for (int j = CRC; j < CPW; ++j) {
                int c = c0 + j;
                sm[WA0 + ((cw * 2 + g) * 32 + l) * SCC + (j - CRC)] =
                    (wrow && c < HD) ? wrow[c] : 0.f;
            }
        }
        if (l < RB0) {
            int r = 64 + l;
            int gate = r / U0, uu = r - gate * U0;
            int gu = cb * U0 + uu;
            const float* wrow = (gu < HD) ? &w_hh[(long long)(gate * HD + gu) * HD] : nullptr;
            for (int j = 0; j < CPW; ++j) {
                int c = c0 + j;
                sm[WB0 + (cw * RB0 + l) * 76 + j] = (wrow && c < HD) ? wrow[c] : 0.f;
            }
        }
    }
    for (int r = tid; r < R0; r += NT) {
        int gate = r / U0, uu = r - gate * U0;
        int gu = cb * U0 + uu;
        long long row = (long long)gate * HD + gu;
        sm[BIAS0 + r] = (gu < HD) ? bi[row] + bh[row] : 0.f;
        sm[WIH0 + r]  = (gu < HD) ? w_ih[row] : 0.f;
    }
    __syncthreads();

    float creg = 0.f;

    for (int t = 0; t < T_STEPS; ++t) {
        const int p = t & 1;
        if (w == 0 && l == 0) {
            poll_ge(&g_cnts[0], (unsigned)t * N0);
            if (t >= 3) poll_ge(&g_cnts[32], (unsigned)(t - 3) * N1);
            FENCE_ACQ();
        }
        __syncthreads();

        if (w >= 1) {
            if (l < NIT) {
                float4 v = __ldcg((const float4*)&g_ha[t & 3][rep][c0 + 4 * l]);
                *(float4*)&sm[HS0 + c0 + 4 * l] = v;
            }
            __syncwarp();
            float a0 = 0.f, a1 = 0.f, ab = 0.f;
            #pragma unroll
            for (int j4 = 0; j4 < NIT; ++j4) {
                float4 hv = *(const float4*)&sm[HS0 + c0 + 4 * j4];
                if (j4 < CRQ) {
                    a0 = fmaf(wr[0][4*j4+0], hv.x, a0); a0 = fmaf(wr[0][4*j4+1], hv.y, a0);
                    a0 = fmaf(wr[0][4*j4+2], hv.z, a0); a0 = fmaf(wr[0][4*j4+3], hv.w, a0);
                    a1 = fmaf(wr[1][4*j4+0], hv.x, a1); a1 = fmaf(wr[1][4*j4+1], hv.y, a1);
                    a1 = fmaf(wr[1][4*j4+2], hv.z, a1); a1 = fmaf(wr[1][4*j4+3], hv.w, a1);
                } else {
                    float4 w0 = *(const float4*)&sm[WA0 + ((cw*2+0)*32+l)*SCC + 4*(j4-CRQ)];
                    float4 w1 = *(const float4*)&sm[WA0 + ((cw*2+1)*32+l)*SCC + 4*(j4-CRQ)];
                    a0 = fmaf(w0.x, hv.x, a0); a0 = fmaf(w0.y, hv.y, a0);
                    a0 = fmaf(w0.z, hv.z, a0); a0 = fmaf(w0.w, hv.w, a0);
                    a1 = fmaf(w1.x, hv.x, a1); a1 = fmaf(w1.y, hv.y, a1);
                    a1 = fmaf(w1.z, hv.z, a1); a1 = fmaf(w1.w, hv.w, a1);
                }
                if (l < RB0) {
                    float4 wb = *(const float4*)&sm[WB0 + (cw*RB0+l)*76 + 4*j4];
                    ab = fmaf(wb.x, hv.x, ab); ab = fmaf(wb.y, hv.y, ab);
                    ab = fmaf(wb.z, hv.z, ab); ab = fmaf(wb.w, hv.w, ab);
                }
            }
            sm[PART0 + (p*NCW + cw)*96 + l]      = a0;
            sm[PART0 + (p*NCW + cw)*96 + 32 + l] = a1;
            if (l < RB0) sm[PART0 + (p*NCW + cw)*96 + 64 + l] = ab;
        }
        __syncthreads();

        if (w == 0) {
            float xv = 0.f;
            if (l == 0) xv = __ldg(&x[t]);
            xv = __shfl_sync(0xffffffffu, xv, 0);
            #pragma unroll
            for (int slot = 0; slot < 3; ++slot) {
                int rr = slot * 32 + l;
                if (rr < R0) {
                    float s = fmaf(xv, sm[WIH0 + rr], sm[BIAS0 + rr]);
                    #pragma unroll
                    for (int c = 0; c < NCW; ++c) s += sm[PART0 + (p*NCW + c)*96 + rr];
                    sm[SUM0 + rr] = s;
                }
            }
            __syncwarp();
            if (l < U0) {
                int u = cb * U0 + l;
                if (u < HD) {
                    float iv = sigm(sm[SUM0 + l]);
                    float fv = sigm(sm[SUM0 + U0 + l]);
                    float gv = tanhf(sm[SUM0 + 2*U0 + l]);
                    float ov = sigm(sm[SUM0 + 3*U0 + l]);
                    float c2 = fmaf(fv, creg, iv * gv);
                    creg = c2;
                    float hh = ov * tanhf(c2);
                    #pragma unroll
                    for (int q = 0; q < RREP; ++q)
                        __stcg(&g_ha[(t + 1) & 3][q][u], hh);
                }
            }
            __syncwarp();
            if (l == 0) RED_INC(&g_cnts[0]);
        }
    }
}

// ================= Layer 1 (94 CTAs) =================
// round t: phase A (ha[t] half, available early: L0 runs ahead) overlaps the
// cnt1 flag flight; then phase B (hb[t-1] half); publish hb[t], RED cnt1.
__device__ void run_l1(int cb,
                       const float* __restrict__ w_hh, const float* __restrict__ w_ih,
                       const float* __restrict__ bi,   const float* __restrict__ bh)
{
    const int tid = threadIdx.x, w = tid >> 5, l = tid & 31;
    const int cw = w - 1;
    const int c0 = cw * CPW;
    const int rep = cb & (RREP - 1);

    float wrB[CRC], wrA[CRC];
    if (w >= 1) {
        {
            int r = l;                                // reg rows 0..31
            int gate = r / U1, uu = r - gate * U1;
            int gu = cb * U1 + uu;
            const float* wB_ = (gu < HD) ? &w_hh[(long long)(gate * HD + gu) * HD] : nullptr;
            const float* wA_ = (gu < HD) ? &w_ih[(long long)(gate * HD + gu) * HD] : nullptr;
            #pragma unroll
            for (int j = 0; j < CRC; ++j) {
                int c = c0 + j;
                wrB[j] = (wB_ && c < HD) ? wB_[c] : 0.f;
                wrA[j] = (wA_ && c < HD) ? wA_[c] : 0.f;
            }
            for (int j = CRC; j < CPW; ++j) {
                int c = c0 + j;
                sm[WAB + (cw*32+l)*SCC + (j-CRC)] = (wB_ && c < HD) ? wB_[c] : 0.f;
                sm[WAA + (cw*32+l)*SCC + (j-CRC)] = (wA_ && c < HD) ? wA_[c] : 0.f;
            }
        }
        if (l < RB1) {
            int r = 32 + l;
            int gate = r / U1, uu = r - gate * U1;
            int gu = cb * U1 + uu;
            const float* wB_ = (gu < HD) ? &w_hh[(long long)(gate * HD + gu) * HD] : nullptr;
            const float* wA_ = (gu < HD) ? &w_ih[(long long)(gate * HD + gu) * HD] : nullptr;
            for (int j = 0; j < CPW; ++j) {
                int c = c0 + j;
                sm[WBM + (cw*RB1+l)*148 + j]      = (wB_ && c < HD) ? wB_[c] : 0.f;
                sm[WBM + (cw*RB1+l)*148 + 72 + j] = (wA_ && c < HD) ? wA_[c] : 0.f;
            }
        }
    }
    for (int r = tid; r < R1; r += NT) {
        int gate = r / U1, uu = r - gate * U1;
        int gu = cb * U1 + uu;
        long long row = (long long)gate * HD + gu;
        sm[BIAS1 + r] = (gu < HD) ? bi[row] + bh[row] : 0.f;
    }
    __syncthreads();

    float creg = 0.f;

    for (int t = 0; t < T_STEPS; ++t) {
        const int p = t & 1;
        // ---- phase A: ha[t] (ring slot (t+1)&3) ----
        if (w == 0 && l == 0) {
            poll_ge(&g_cnts[0], (unsigned)(t + 1) * N0);
            FENCE_ACQ();
        }
        __syncthreads();
        float a0 = 0.f, ab = 0.f;
        if (w >= 1) {
            if (l < NIT) {
                float4 v = __ldcg((const float4*)&g_ha[(t + 1) & 3][rep][c0 + 4 * l]);
                *(float4*)&sm[HSA + c0 + 4 * l] = v;
            }
            __syncwarp();
            #pragma unroll
            for (int j4 = 0; j4 < NIT; ++j4) {
                float4 hv = *(const float4*)&sm[HSA + c0 + 4 * j4];
                if (j4 < CRQ) {
                    a0 = fmaf(wrA[4*j4+0], hv.x, a0); a0 = fmaf(wrA[4*j4+1], hv.y, a0);
                    a0 = fmaf(wrA[4*j4+2], hv.z, a0); a0 = fmaf(wrA[4*j4+3], hv.w, a0);
                } else {
                    float4 wv = *(const float4*)&sm[WAA + (cw*32+l)*SCC + 4*(j4-CRQ)];
                    a0 = fmaf(wv.x, hv.x, a0); a0 = fmaf(wv.y, hv.y, a0);
                    a0 = fmaf(wv.z, hv.z, a0); a0 = fmaf(wv.w, hv.w, a0);
                }
                if (l < RB1) {
                    float4 wv = *(const float4*)&sm[WBM + (cw*RB1+l)*148 + 72 + 4*j4];
                    ab = fmaf(wv.x, hv.x, ab); ab = fmaf(wv.y, hv.y, ab);
                    ab = fmaf(wv.z, hv.z, ab); ab = fmaf(wv.w, hv.w, ab);
                }
            }
        }
        // ---- phase B: hb[t-1] (ring slot t&3) ----
        if (w == 0 && l == 0) {
            poll_ge(&g_cnts[32], (unsigned)t * N1);
            FENCE_ACQ();
        }
        __syncthreads();
        if (w >= 1) {
            if (l < NIT) {
                float4 v = __ldcg((const float4*)&g_hb[t & 3][rep][c0 + 4 * l]);
                *(float4*)&sm[HSB + c0 + 4 * l] = v;
            }
            __syncwarp();
            #pragma unroll
            for (int j4 = 0; j4 < NIT; ++j4) {
                float4 hv = *(const float4*)&sm[HSB + c0 + 4 * j4];
                if (j4 < CRQ) {
                    a0 = fmaf(wrB[4*j4+0], hv.x, a0); a0 = fmaf(wrB[4*j4+1], hv.y, a0);
                    a0 = fmaf(wrB[4*j4+2], hv.z, a0); a0 = fmaf(wrB[4*j4+3], hv.w, a0);
                } else {
                    float4 wv = *(const float4*)&sm[WAB + (cw*32+l)*SCC + 4*(j4-CRQ)];
                    a0 = fmaf(wv.x, hv.x, a0); a0 = fmaf(wv.y, hv.y, a0);
                    a0 = fmaf(wv.z, hv.z, a0); a0 = fmaf(wv.w, hv.w, a0);
                }
                if (l < RB1) {
                    float4 wv = *(const float4*)&sm[WBM + (cw*RB1+l)*148 + 4*j4];
                    ab = fmaf(wv.x, hv.x, ab); ab = fmaf(wv.y, hv.y, ab);
                    ab = fmaf(wv.z, hv.z, ab); ab = fmaf(wv.w, hv.w, ab);
                }
            }
            sm[PART1 + (p*NCW + cw)*48 + l] = a0;
            if (l < RB1) sm[PART1 + (p*NCW + cw)*48 + 32 + l] = ab;
        }
        __syncthreads();

        if (w == 0) {
            #pragma unroll
            for (int slot = 0; slot < 2; ++slot) {
                int rr = slot * 32 + l;
                if (rr < R1) {
                    float s = sm[BIAS1 + rr];
                    #pragma unroll
                    for (int c = 0; c < NCW; ++c) s += sm[PART1 + (p*NCW + c)*48 + rr];
                    sm[SUM1 + rr] = s;
                }
            }
            __syncwarp();
            if (l < U1) {
                int u = cb * U1 + l;
                if (u < HD) {
                    float iv = sigm(sm[SUM1 + l]);
                    float fv = sigm(sm[SUM1 + U1 + l]);
                    float gv = tanhf(sm[SUM1 + 2*U1 + l]);
                    float ov = sigm(sm[SUM1 + 3*U1 + l]);
                    float c2 = fmaf(fv, creg, iv * gv);
                    creg = c2;
                    float hh = ov * tanhf(c2);
                    #pragma unroll
                    for (int q = 0; q < RREP; ++q)
                        __stcg(&g_hb[(t + 1) & 3][q][u], hh);
                    g_h2[(long long)t * HD + u] = hh;
                }
            }
            __syncwarp();
            if (l == 0) RED_INC(&g_cnts[32]);
        }
    }
}

__global__ void __launch_bounds__(NT, 1) fused_lstm_kernel(
    const float* __restrict__ x,
    const float* __restrict__ w_ih0, const float* __restrict__ w_hh0,
    const float* __restrict__ b_ih0, const float* __restrict__ b_hh0,
    const float* __restrict__ w_ih1, const float* __restrict__ w_hh1,
    const float* __restrict__ b_ih1, const float* __restrict__ b_hh1)
{
    if (blockIdx.x < N0)
        run_l0(blockIdx.x, w_hh0, w_ih0, b_ih0, b_hh0, x);
    else
        run_l1(blockIdx.x - N0, w_hh1, w_ih1, b_ih1, b_hh1);
}

// ---------------- final linear: out[t] = h2[t] . lin_w + lin_b ----------------
__global__ void outdot_kernel(const float* __restrict__ lw,
                              const float* __restrict__ lb,
                              float* __restrict__ out)
{
    const int w = threadIdx.x >> 5;
    const int l = threadIdx.x & 31;
    const int t = blockIdx.x * 4 + w;
    if (t >= T_STEPS) return;
    const float* h = g_h2 + (long long)t * HD;
    float acc = 0.f;
    for (int u = l; u < HD; u += 32) acc = fmaf(h[u], lw[u], acc);
    #pragma unroll
    for (int o = 16; o; o >>= 1) acc += __shfl_down_sync(0xffffffffu, acc, o);
    if (l == 0) out[t] = acc + lb[0];
}

// ---------------- launch ----------------
extern "C" void kernel_launch(void* const* d_in, const int* in_sizes, int n_in,
                              void* d_out, int out_size)
{
    const float* x     = (const float*)d_in[0];
    const float* w_ih0 = (const float*)d_in[1];
    const float* w_hh0 = (const float*)d_in[2];
    const float* b_ih0 = (const float*)d_in[3];
    const float* b_hh0 = (const float*)d_in[4];
    const float* w_ih1 = (const float*)d_in[5];
    const float* w_hh1 = (const float*)d_in[6];
    const float* b_ih1 = (const float*)d_in[7];
    const float* b_hh1 = (const float*)d_in[8];
    const float* lin_w = (const float*)d_in[9];
    const float* lin_b = (const float*)d_in[10];
    float* out = (float*)d_out;

    void *p_ha, *p_hb, *p_cnts;
    cudaGetSymbolAddress(&p_ha,   g_ha);
    cudaGetSymbolAddress(&p_hb,   g_hb);
    cudaGetSymbolAddress(&p_cnts, g_cnts);

    // zero rings (h[-1]=0 + pad) and both round counters (per-replay reset)
    cudaMemsetAsync(p_ha,   0, sizeof(float) * RING * RREP * RSTR);
    cudaMemsetAsync(p_hb,   0, sizeof(float) * RING * RREP * RSTR);
    cudaMemsetAsync(p_cnts, 0, sizeof(unsigned) * 64);

    cudaFuncSetAttribute(fused_lstm_kernel,
                         cudaFuncAttributeMaxDynamicSharedMemorySize, SMEM_BYTES);

    fused_lstm_kernel<<<NCTA, NT, SMEM_BYTES>>>(
        x, w_ih0, w_hh0, b_ih0, b_hh0, w_ih1, w_hh1, b_ih1, b_hh1);

    outdot_kernel<<<(T_STEPS + 3) / 4, 128>>>(lin_w, lin_b, out);
}

// round 15
// speedup vs baseline: 1.2664x; 1.2664x over previous
#include <cuda_runtime.h>
#include <math.h>

// ---------------- problem constants ----------------
#define T_STEPS 16384
#define HD      1028
#define NT      512          // 16 warps, all compute; warp0 also does the tail
#define NWP     16

// Layer 0: 49 CTAs x 21 units (84 rows = 64 reg + 20 smem)
#define N0  49
#define U0  21
#define R0  84
#define RB0 20
// Layer 1: 94 CTAs x 11 units (44 rows = 32 reg + 12 smem)
#define N1  94
#define U1  11
#define R1  44
#define RB1 12

#define CPW 68               // cols per warp: 16*68 = 1088 >= 1028
#define NIT 17               // float4 iters per chunk
#define CRQ 11               // reg-col float4 iters (44 cols in regs)
#define CRC 44
#define SCC 24               // smem cols per reg-row (68-44)
#define VL  1088             // padded vector length
#define RING 4
#define RREP 4
#define NCTA (N0 + N1)       // 143

// ---- L0 smem offsets (floats) ----
#define HS0   0
#define WA0   1088
#define WB0   (WA0 + NWP*2*32*SCC)     // 25664
#define PART0 (WB0 + NWP*RB0*76)       // 49984  ([2][16][96])
#define SUM0  (PART0 + 2*NWP*96)       // 53056
#define BIAS0 (SUM0 + 96)
#define WIH0  (BIAS0 + 96)
#define END0  (WIH0 + 96)              // 53344
// ---- L1 smem offsets ----
#define HSB   0
#define HSA   1088
#define WAB   2176
#define WAA   (WAB + NWP*32*SCC)       // 14464
#define WBM   (WAA + NWP*32*SCC)       // 26752  ([16][12][148]: B at +0, A at +72)
#define PART1 (WBM + NWP*RB1*148)      // 55168  ([2][16][48])
#define SUM1  (PART1 + 2*NWP*48)       // 56704
#define BIAS1 (SUM1 + 48)
#define END1  (BIAS1 + 48)             // 56800
#define SMEM_BYTES (END1 * 4)          // 227,200 B

// ---------------- device scratch ----------------
// h broadcast: {fp32 value (lo), u32 epoch (hi)} per element. 8B atomicity
// makes value+epoch always consistent -> poll data directly, zero fences.
__device__ unsigned long long g_ha[RING][RREP][VL];
__device__ unsigned long long g_hb[RING][RREP][VL];
__device__ __align__(16) float g_h2[(long long)T_STEPS * HD];
__device__ unsigned g_cnts[64];   // [0]=cnt0 (L0 consume), [32]=cnt1 (L1 consume)

extern __shared__ float sm[];

__device__ __forceinline__ unsigned long long ldx(const unsigned long long* p) {
    unsigned long long v;
    asm volatile("ld.relaxed.gpu.global.b64 %0, [%1];" : "=l"(v) : "l"(p) : "memory");
    return v;
}
__device__ __forceinline__ void stx(unsigned long long* p, unsigned long long v) {
    asm volatile("st.relaxed.gpu.global.b64 [%0], %1;" :: "l"(p), "l"(v) : "memory");
}
__device__ __forceinline__ void red_inc(unsigned* p) {
    asm volatile("red.release.gpu.global.add.u32 [%0], %1;" :: "l"(p), "r"(1u) : "memory");
}
__device__ __forceinline__ void poll_ge(unsigned* p, unsigned tgt) {
    unsigned v;
    do {
        asm volatile("ld.relaxed.gpu.global.u32 %0, [%1];" : "=r"(v) : "l"(p) : "memory");
    } while (v < tgt);
}
__device__ __forceinline__ float sigm(float v) { return 1.f / (1.f + expf(-v)); }

// Per-warp: spin on own 68-atom chunk until all epochs == ep, then write the
// values (already in regs from the matching load) to smem. Detection == fetch.
__device__ __forceinline__ void stage_chunk(const unsigned long long* buf,
                                            unsigned ep, float* dst,
                                            int c0, int l)
{
    const int i1 = c0 + l, i2 = c0 + 32 + l, i3 = c0 + 64 + l;
    const bool n1 = i1 < HD, n2 = i2 < HD, n3 = (l < 4) && (i3 < HD);
    unsigned long long v1 = 0, v2 = 0, v3 = 0;
    for (;;) {
        if (n1) v1 = ldx(buf + i1);
        if (n2) v2 = ldx(buf + i2);
        if (n3) v3 = ldx(buf + i3);
        bool ok = (!n1 || (unsigned)(v1 >> 32) == ep)
               && (!n2 || (unsigned)(v2 >> 32) == ep)
               && (!n3 || (unsigned)(v3 >> 32) == ep);
        if (__all_sync(0xffffffffu, ok)) break;
    }
    dst[i1] = n1 ? __uint_as_float((unsigned)v1) : 0.f;
    dst[i2] = n2 ? __uint_as_float((unsigned)v2) : 0.f;
    if (l < 4) dst[i3] = n3 ? __uint_as_float((unsigned)v3) : 0.f;
    __syncwarp();
}

__device__ __forceinline__ unsigned long long packh(float v, unsigned ep) {
    return ((unsigned long long)ep << 32) | (unsigned long long)__float_as_uint(v);
}

// ================= Layer 0 (49 CTAs) =================
// round t: stage ha epoch t (slot t&3) via data-poll; compute; warp0 publishes
// ha epoch t+1 into slot (t+1)&3. cnt0 RED at consume; back-pressure polls
// (3-round slack) before overwrite.
__device__ void run_l0(int cb,
                       const float* __restrict__ w_hh, const float* __restrict__ w_ih,
                       const float* __restrict__ bi,   const float* __restrict__ bh,
                       const float* __restrict__ x)
{
    const int tid = threadIdx.x, w = tid >> 5, l = tid & 31;
    const int c0 = w * CPW;
    const int rep = cb & (RREP - 1);

    float wr[2][CRC];
    #pragma unroll
    for (int g = 0; g < 2; ++g) {
        int r = g * 32 + l;
        int gate = r / U0, uu = r - gate * U0;
        int gu = cb * U0 + uu;
        const float* wrow = (gu < HD) ? &w_hh[(long long)(gate * HD + gu) * HD] : nullptr;
        #pragma unroll
        for (int j = 0; j < CRC; ++j) {
            int c = c0 + j;
            wr[g][j] = (wrow && c < HD) ? wrow[c] : 0.f;
        }
        for (int j = CRC; j < CPW; ++j) {
            int c = c0 + j;
            sm[WA0 + ((w * 2 + g) * 32 + l) * SCC + (j - CRC)] =
                (wrow && c < HD) ? wrow[c] : 0.f;
        }
    }
    if (l < RB0) {
        int r = 64 + l;
        int gate = r / U0, uu = r - gate * U0;
        int gu = cb * U0 + uu;
        const float* wrow = (gu < HD) ? &w_hh[(long long)(gate * HD + gu) * HD] : nullptr;
        for (int j = 0; j < CPW; ++j) {
            int c = c0 + j;
            sm[WB0 + (w * RB0 + l) * 76 + j] = (wrow && c < HD) ? wrow[c] : 0.f;
        }
    }
    for (int r = tid; r < R0; r += NT) {
        int gate = r / U0, uu = r - gate * U0;
        int gu = cb * U0 + uu;
        long long row = (long long)gate * HD + gu;
        sm[BIAS0 + r] = (gu < HD) ? bi[row] + bh[row] : 0.f;
        sm[WIH0 + r]  = (gu < HD) ? w_ih[row] : 0.f;
    }
    __syncthreads();

    float creg = 0.f;

    for (int t = 0; t < T_STEPS; ++t) {
        const int p = t & 1;

        // ---- stage ha[t] by polling data epochs (no barrier, no fence) ----
        stage_chunk(&g_ha[t & 3][rep][0], (unsigned)t, sm + HS0, c0, l);

        // ---- partial dots ----
        float a0 = 0.f, a1 = 0.f, ab = 0.f;
        #pragma unroll
        for (int j4 = 0; j4 < NIT; ++j4) {
            float4 hv = *(const float4*)&sm[HS0 + c0 + 4 * j4];
            if (j4 < CRQ) {
                a0 = fmaf(wr[0][4*j4+0], hv.x, a0); a0 = fmaf(wr[0][4*j4+1], hv.y, a0);
                a0 = fmaf(wr[0][4*j4+2], hv.z, a0); a0 = fmaf(wr[0][4*j4+3], hv.w, a0);
                a1 = fmaf(wr[1][4*j4+0], hv.x, a1); a1 = fmaf(wr[1][4*j4+1], hv.y, a1);
                a1 = fmaf(wr[1][4*j4+2], hv.z, a1); a1 = fmaf(wr[1][4*j4+3], hv.w, a1);
            } else {
                float4 w0 = *(const float4*)&sm[WA0 + ((w*2+0)*32+l)*SCC + 4*(j4-CRQ)];
                float4 w1 = *(const float4*)&sm[WA0 + ((w*2+1)*32+l)*SCC + 4*(j4-CRQ)];
                a0 = fmaf(w0.x, hv.x, a0); a0 = fmaf(w0.y, hv.y, a0);
                a0 = fmaf(w0.z, hv.z, a0); a0 = fmaf(w0.w, hv.w, a0);
                a1 = fmaf(w1.x, hv.x, a1); a1 = fmaf(w1.y, hv.y, a1);
                a1 = fmaf(w1.z, hv.z, a1); a1 = fmaf(w1.w, hv.w, a1);
            }
            if (l < RB0) {
                float4 wb = *(const float4*)&sm[WB0 + (w*RB0+l)*76 + 4*j4];
                ab = fmaf(wb.x, hv.x, ab); ab = fmaf(wb.y, hv.y, ab);
                ab = fmaf(wb.z, hv.z, ab); ab = fmaf(wb.w, hv.w, ab);
            }
        }
        sm[PART0 + (p*NWP + w)*96 + l]      = a0;
        sm[PART0 + (p*NWP + w)*96 + 32 + l] = a1;
        if (l < RB0) sm[PART0 + (p*NWP + w)*96 + 64 + l] = ab;
        __syncthreads();

        if (w == 0) {
            if (l == 0) {
                red_inc(&g_cnts[0]);   // consumed ha[t]
                // back-pressure before overwriting slot (t+1)&3 (epoch t-3)
                if (t >= 3) poll_ge(&g_cnts[0],  (unsigned)(t - 2) * N0);
                if (t >= 4) poll_ge(&g_cnts[32], (unsigned)(t - 3) * N1);
            }
            float xv = 0.f;
            if (l == 0) xv = __ldg(&x[t]);
            xv = __shfl_sync(0xffffffffu, xv, 0);
            #pragma unroll
            for (int slot = 0; slot < 3; ++slot) {
                int rr = slot * 32 + l;
                if (rr < R0) {
                    float s = fmaf(xv, sm[WIH0 + rr], sm[BIAS0 + rr]);
                    #pragma unroll
                    for (int c = 0; c < NWP; ++c) s += sm[PART0 + (p*NWP + c)*96 + rr];
                    sm[SUM0 + rr] = s;
                }
            }
            __syncwarp();
            if (l < U0) {
                int u = cb * U0 + l;
                if (u < HD) {
                    float iv = sigm(sm[SUM0 + l]);
                    float fv = sigm(sm[SUM0 + U0 + l]);
                    float gv = tanhf(sm[SUM0 + 2*U0 + l]);
                    float ov = sigm(sm[SUM0 + 3*U0 + l]);
                    float c2 = fmaf(fv, creg, iv * gv);
                    creg = c2;
                    unsigned long long pk = packh(ov * tanhf(c2), (unsigned)(t + 1));
                    #pragma unroll
                    for (int q = 0; q < RREP; ++q)
                        stx(&g_ha[(t + 1) & 3][q][u], pk);
                }
            }
        }
    }
}

// ================= Layer 1 (94 CTAs) =================
// round t: stage ha epoch t+1 (L0 runs ahead -> usually immediate), compute A;
// stage hb epoch t, compute B; warp0 publishes hb epoch t+1 + g_h2[t].
__device__ void run_l1(int cb,
                       const float* __restrict__ w_hh, const float* __restrict__ w_ih,
                       const float* __restrict__ bi,   const float* __restrict__ bh)
{
    const int tid = threadIdx.x, w = tid >> 5, l = tid & 31;
    const int c0 = w * CPW;
    const int rep = cb & (RREP - 1);

    float wrB[CRC], wrA[CRC];
    {
        int r = l;
        int gate = r / U1, uu = r - gate * U1;
        int gu = cb * U1 + uu;
        const float* wB_ = (gu < HD) ? &w_hh[(long long)(gate * HD + gu) * HD] : nullptr;
        const float* wA_ = (gu < HD) ? &w_ih[(long long)(gate * HD + gu) * HD] : nullptr;
        #pragma unroll
        for (int j = 0; j < CRC; ++j) {
            int c = c0 + j;
            wrB[j] = (wB_ && c < HD) ? wB_[c] : 0.f;
            wrA[j] = (wA_ && c < HD) ? wA_[c] : 0.f;
        }
        for (int j = CRC; j < CPW; ++j) {
            int c = c0 + j;
            sm[WAB + (w*32+l)*SCC + (j-CRC)] = (wB_ && c < HD) ? wB_[c] : 0.f;
            sm[WAA + (w*32+l)*SCC + (j-CRC)] = (wA_ && c < HD) ? wA_[c] : 0.f;
        }
    }
    if (l < RB1) {
        int r = 32 + l;
        int gate = r / U1, uu = r - gate * U1;
        int gu = cb * U1 + uu;
        const float* wB_ = (gu < HD) ? &w_hh[(long long)(gate * HD + gu) * HD] : nullptr;
        const float* wA_ = (gu < HD) ? &w_ih[(long long)(gate * HD + gu) * HD] : nullptr;
        for (int j = 0; j < CPW; ++j) {
            int c = c0 + j;
            sm[WBM + (w*RB1+l)*148 + j]      = (wB_ && c < HD) ? wB_[c] : 0.f;
            sm[WBM + (w*RB1+l)*148 + 72 + j] = (wA_ && c < HD) ? wA_[c] : 0.f;
        }
    }
    for (int r = tid; r < R1; r += NT) {
        int gate = r / U1, uu = r - gate * U1;
        int gu = cb * U1 + uu;
        long long row = (long long)gate * HD + gu;
        sm[BIAS1 + r] = (gu < HD) ? bi[row] + bh[row] : 0.f;
    }
    __syncthreads();

    float creg = 0.f;

    for (int t = 0; t < T_STEPS; ++t) {
        const int p = t & 1;
        float a0 = 0.f, ab = 0.f;

        // ---- phase A: ha epoch t+1 (slot (t+1)&3) ----
        stage_chunk(&g_ha[(t + 1) & 3][rep][0], (unsigned)(t + 1), sm + HSA, c0, l);
        #pragma unroll
        for (int j4 = 0; j4 < NIT; ++j4) {
            float4 hv = *(const float4*)&sm[HSA + c0 + 4 * j4];
            if (j4 < CRQ) {
                a0 = fmaf(wrA[4*j4+0], hv.x, a0); a0 = fmaf(wrA[4*j4+1], hv.y, a0);
                a0 = fmaf(wrA[4*j4+2], hv.z, a0); a0 = fmaf(wrA[4*j4+3], hv.w, a0);
            } else {
                float4 wv = *(const float4*)&sm[WAA + (w*32+l)*SCC + 4*(j4-CRQ)];
                a0 = fmaf(wv.x, hv.x, a0); a0 = fmaf(wv.y, hv.y, a0);
                a0 = fmaf(wv.z, hv.z, a0); a0 = fmaf(wv.w, hv.w, a0);
            }
            if (l < RB1) {
                float4 wv = *(const float4*)&sm[WBM + (w*RB1+l)*148 + 72 + 4*j4];
                ab = fmaf(wv.x, hv.x, ab); ab = fmaf(wv.y, hv.y, ab);
                ab = fmaf(wv.z, hv.z, ab); ab = fmaf(wv.w, hv.w, ab);
            }
        }

        // ---- phase B: hb epoch t (slot t&3) ----
        stage_chunk(&g_hb[t & 3][rep][0], (unsigned)t, sm + HSB, c0, l);
        #pragma unroll
        for (int j4 = 0; j4 < NIT; ++j4) {
            float4 hv = *(const float4*)&sm[HSB + c0 + 4 * j4];
            if (j4 < CRQ) {
                a0 = fmaf(wrB[4*j4+0], hv.x, a0); a0 = fmaf(wrB[4*j4+1], hv.y, a0);
                a0 = fmaf(wrB[4*j4+2], hv.z, a0); a0 = fmaf(wrB[4*j4+3], hv.w, a0);
            } else {
                float4 wv = *(const float4*)&sm[WAB + (w*32+l)*SCC + 4*(j4-CRQ)];
                a0 = fmaf(wv.x, hv.x, a0); a0 = fmaf(wv.y, hv.y, a0);
                a0 = fmaf(wv.z, hv.z, a0); a0 = fmaf(wv.w, hv.w, a0);
            }
            if (l < RB1) {
                float4 wv = *(const float4*)&sm[WBM + (w*RB1+l)*148 + 4*j4];
                ab = fmaf(wv.x, hv.x, ab); ab = fmaf(wv.y, hv.y, ab);
                ab = fmaf(wv.z, hv.z, ab); ab = fmaf(wv.w, hv.w, ab);
            }
        }
        sm[PART1 + (p*NWP + w)*48 + l] = a0;
        if (l < RB1) sm[PART1 + (p*NWP + w)*48 + 32 + l] = ab;
        __syncthreads();

        if (w == 0) {
            if (l == 0) {
                red_inc(&g_cnts[32]);  // consumed ha[t+1] + hb[t]
                // back-pressure before overwriting hb slot (t+1)&3 (epoch t-3)
                if (t >= 3) poll_ge(&g_cnts[32], (unsigned)(t - 2) * N1);
            }
            #pragma unroll
            for (int slot = 0; slot < 2; ++slot) {
                int rr = slot * 32 + l;
                if (rr < R1) {
                    float s = sm[BIAS1 + rr];
                    #pragma unroll
                    for (int c = 0; c < NWP; ++c) s += sm[PART1 + (p*NWP + c)*48 + rr];
                    sm[SUM1 + rr] = s;
                }
            }
            __syncwarp();
            if (l < U1) {
                int u = cb * U1 + l;
                if (u < HD) {
                    float iv = sigm(sm[SUM1 + l]);
                    float fv = sigm(sm[SUM1 + U1 + l]);
                    float gv = tanhf(sm[SUM1 + 2*U1 + l]);
                    float ov = sigm(sm[SUM1 + 3*U1 + l]);
                    float c2 = fmaf(fv, creg, iv * gv);
                    creg = c2;
                    float hh = ov * tanhf(c2);
                    unsigned long long pk = packh(hh, (unsigned)(t + 1));
                    #pragma unroll
                    for (int q = 0; q < RREP; ++q)
                        stx(&g_hb[(t + 1) & 3][q][u], pk);
                    g_h2[(long long)t * HD + u] = hh;
                }
            }
        }
    }
}

__global__ void __launch_bounds__(NT, 1) fused_lstm_kernel(
    const float* __restrict__ x,
    const float* __restrict__ w_ih0, const float* __restrict__ w_hh0,
    const float* __restrict__ b_ih0, const float* __restrict__ b_hh0,
    const float* __restrict__ w_ih1, const float* __restrict__ w_hh1,
    const float* __restrict__ b_ih1, const float* __restrict__ b_hh1)
{
    if (blockIdx.x < N0)
        run_l0(blockIdx.x, w_hh0, w_ih0, b_ih0, b_hh0, x);
    else
        run_l1(blockIdx.x - N0, w_hh1, w_ih1, b_ih1, b_hh1);
}

// ---------------- final linear: out[t] = h2[t] . lin_w + lin_b ----------------
__global__ void outdot_kernel(const float* __restrict__ lw,
                              const float* __restrict__ lb,
                              float* __restrict__ out)
{
    const int w = threadIdx.x >> 5;
    const int l = threadIdx.x & 31;
    const int t = blockIdx.x * 4 + w;
    if (t >= T_STEPS) return;
    const float* h = g_h2 + (long long)t * HD;
    float acc = 0.f;
    for (int u = l; u < HD; u += 32) acc = fmaf(h[u], lw[u], acc);
    #pragma unroll
    for (int o = 16; o; o >>= 1) acc += __shfl_down_sync(0xffffffffu, acc, o);
    if (l == 0) out[t] = acc + lb[0];
}

// ---------------- launch ----------------
extern "C" void kernel_launch(void* const* d_in, const int* in_sizes, int n_in,
                              void* d_out, int out_size)
{
    const float* x     = (const float*)d_in[0];
    const float* w_ih0 = (const float*)d_in[1];
    const float* w_hh0 = (const float*)d_in[2];
    const float* b_ih0 = (const float*)d_in[3];
    const float* b_hh0 = (const float*)d_in[4];
    const float* w_ih1 = (const float*)d_in[5];
    const float* w_hh1 = (const float*)d_in[6];
    const float* b_ih1 = (const float*)d_in[7];
    const float* b_hh1 = (const float*)d_in[8];
    const float* lin_w = (const float*)d_in[9];
    const float* lin_b = (const float*)d_in[10];
    float* out = (float*)d_out;

    void *p_ha, *p_hb, *p_cnts;
    cudaGetSymbolAddress(&p_ha,   g_ha);
    cudaGetSymbolAddress(&p_hb,   g_hb);
    cudaGetSymbolAddress(&p_cnts, g_cnts);

    // zero rings (value 0 + epoch 0 == exact initial state) and counters
    cudaMemsetAsync(p_ha,   0, sizeof(unsigned long long) * RING * RREP * VL);
    cudaMemsetAsync(p_hb,   0, sizeof(unsigned long long) * RING * RREP * VL);
    cudaMemsetAsync(p_cnts, 0, sizeof(unsigned) * 64);

    cudaFuncSetAttribute(fused_lstm_kernel,
                         cudaFuncAttributeMaxDynamicSharedMemorySize, SMEM_BYTES);

    fused_lstm_kernel<<<NCTA, NT, SMEM_BYTES>>>(
        x, w_ih0, w_hh0, b_ih0, b_hh0, w_ih1, w_hh1, b_ih1, b_hh1);

    outdot_kernel<<<(T_STEPS + 3) / 4, 128>>>(lin_w, lin_b, out);
}